// round 8
// baseline (speedup 1.0000x reference)
#include <cuda_runtime.h>
#include <cuda_bf16.h>
#include <cstdint>
#include <cstring>

// Problem constants
#define DDIM   4096
#define TOPK   2048
#define NMASK  64
#define PBOUND 1024
#define MDIM   4096      // B*S
#define NDIM   4096      // O

// GEMM tiling: 128x128x32, 3-stage cp.async, 2 CTAs/SM
#define BM 128
#define BN 128
#define BK 32
#define STAGES 3
#define TILE_B (BM * BK * 2)           // 8192 bytes per bf16 tile (128 x 32)
#define STAGE_B (4 * TILE_B)           // Ah, Al, Wh, Wl = 32768
#define SMEM_TOTAL (STAGES * STAGE_B)  // 98304 (x2 CTAs = 192KB < 228KB)

// ---------------------------------------------------------------------------
// Device-global scratch (allocation-free rule)
// ---------------------------------------------------------------------------
__device__ __align__(16) float g_fmask[DDIM];
__device__ unsigned char g_topk[DDIM];
__device__ int g_perm_mode;     // 8 = int64 storage, 4 = int32
__device__ int g_mask_mode;     // 1 = uint8, 4 = int32, 5 = float32
__device__ int g_kidx[DDIM];    // compacted active K indices (sorted) + padding
__device__ int g_kpad;          // active count padded to multiple of BK
__device__ __align__(16) __nv_bfloat16 g_Ah[(size_t)MDIM * DDIM];
__device__ __align__(16) __nv_bfloat16 g_Al[(size_t)MDIM * DDIM];
__device__ __align__(16) __nv_bfloat16 g_Wh[(size_t)NDIM * DDIM];
__device__ __align__(16) __nv_bfloat16 g_Wl[(size_t)NDIM * DDIM];

// ---------------------------------------------------------------------------
// PTX helpers (baseline sm_80+ features only)
// ---------------------------------------------------------------------------
__device__ __forceinline__ uint32_t smem_u32(const void* p) {
    uint32_t a;
    asm("{ .reg .u64 t; cvta.to.shared.u64 t, %1; cvt.u32.u64 %0, t; }"
        : "=r"(a) : "l"(p));
    return a;
}
__device__ __forceinline__ void cp16(uint32_t dst, const void* src) {
    asm volatile("cp.async.cg.shared.global [%0], [%1], 16;"
                 :: "r"(dst), "l"(src) : "memory");
}
__device__ __forceinline__ void cp_commit() {
    asm volatile("cp.async.commit_group;" ::: "memory");
}
template <int N>
__device__ __forceinline__ void cp_wait() {
    asm volatile("cp.async.wait_group %0;" :: "n"(N) : "memory");
}
__device__ __forceinline__ void ldsm4(uint32_t* r, uint32_t addr) {
    asm volatile("ldmatrix.sync.aligned.m8n8.x4.shared.b16 {%0,%1,%2,%3}, [%4];"
                 : "=r"(r[0]), "=r"(r[1]), "=r"(r[2]), "=r"(r[3]) : "r"(addr));
}
__device__ __forceinline__ void mma_bf16(float* c, const uint32_t* a,
                                         uint32_t b0, uint32_t b1) {
    asm volatile(
        "mma.sync.aligned.m16n8k16.row.col.f32.bf16.bf16.f32 "
        "{%0,%1,%2,%3}, {%4,%5,%6,%7}, {%8,%9}, {%0,%1,%2,%3};"
        : "+f"(c[0]), "+f"(c[1]), "+f"(c[2]), "+f"(c[3])
        : "r"(a[0]), "r"(a[1]), "r"(a[2]), "r"(a[3]), "r"(b0), "r"(b1));
}
// Swizzled byte offset inside a 128x32-bf16 tile (64B rows, 4x16B chunks).
__device__ __forceinline__ uint32_t tile_off(int row, int chunk) {
    return (uint32_t)row * 64u + (uint32_t)((chunk ^ ((row >> 1) & 3)) * 16);
}

// ---------------------------------------------------------------------------
// Kernel 0: dtype detection (deterministic), parallelized to 256 threads
// ---------------------------------------------------------------------------
__global__ void detect_kernel(const void* __restrict__ perm,
                              const void* __restrict__ masks) {
    __shared__ int s_zero[8], s_f32[8];
    __shared__ unsigned int s_max[8];
    int tid = threadIdx.x, wid = tid >> 5, lane = tid & 31;

    // perm: count zero odd-words among first 4096 int32 words
    const int* p32 = (const int*)perm;
    int zeros = 0;
    for (int i = 1 + 2 * tid; i < 4096; i += 512) zeros += (p32[i] == 0);

    // masks: scan first 1024 int32 words
    const unsigned int* m32 = (const unsigned int*)masks;
    int has_f32 = 0;
    unsigned int maxv = 0;
    for (int i = tid; i < 1024; i += 256) {
        unsigned int v = m32[i];
        if (v == 0x3F800000u) has_f32 = 1;
        if (v > maxv) maxv = v;
    }
#pragma unroll
    for (int off = 16; off > 0; off >>= 1) {
        zeros   += __shfl_down_sync(0xffffffffu, zeros, off);
        has_f32 |= __shfl_down_sync(0xffffffffu, has_f32, off);
        unsigned int o = __shfl_down_sync(0xffffffffu, maxv, off);
        if (o > maxv) maxv = o;
    }
    if (lane == 0) { s_zero[wid] = zeros; s_f32[wid] = has_f32; s_max[wid] = maxv; }
    __syncthreads();
    if (tid == 0) {
        int z = 0, f = 0;
        unsigned int mx = 0;
        for (int i = 0; i < 8; i++) {
            z += s_zero[i];
            f |= s_f32[i];
            if (s_max[i] > mx) mx = s_max[i];
        }
        g_perm_mode = (z >= 1000) ? 8 : 4;
        g_mask_mode = f ? 5 : (mx <= 1u ? 4 : 1);
    }
}

__device__ __forceinline__ int mask_at(const void* masks, int mode, size_t idx) {
    if (mode == 1) return ((const unsigned char*)masks)[idx] != 0;
    if (mode == 4) return ((const int*)masks)[idx] != 0;
    return ((const float*)masks)[idx] != 0.0f;
}

// ---------------------------------------------------------------------------
// Kernel 1: exact top-k membership by rank counting
// ---------------------------------------------------------------------------
__global__ void topk_kernel(const float* __restrict__ x) {
    __shared__ float a[DDIM];
    const float* f0 = x + (size_t)PBOUND * DDIM;
    for (int i = threadIdx.x; i < DDIM; i += blockDim.x) a[i] = fabsf(f0[i]);
    __syncthreads();

    int d = blockIdx.x * blockDim.x + threadIdx.x;
    float ad = a[d];
    int cnt = 0;
#pragma unroll 8
    for (int e = 0; e < DDIM; e++) {
        float ae = a[e];
        cnt += (int)((ae > ad) || (ae == ad && e < d));
    }
    g_topk[d] = (cnt < TOPK) ? 1u : 0u;
}

// ---------------------------------------------------------------------------
// Kernel 2: mask selection + gate -> g_fmask, plus K compaction -> g_kidx/kpad
// ---------------------------------------------------------------------------
__global__ void select_kernel(const void* __restrict__ masks,
                              const void* __restrict__ perm) {
    __shared__ int counts[NMASK];
    __shared__ int sbest, sflag;
    __shared__ int scan[1024];
    __shared__ int s_inactive;

    int pmode = g_perm_mode, mmode = g_mask_mode;
    int tid = threadIdx.x, j = tid >> 4, lane = tid & 15;

    int partial = 0;
    for (int d = lane; d < DDIM; d += 16) {
        if (g_topk[d]) {
            int p = (pmode == 8) ? (int)((const long long*)perm)[d]
                                 : ((const int*)perm)[d];
            partial += mask_at(masks, mmode, (size_t)j * DDIM + p);
        }
    }
#pragma unroll
    for (int off = 8; off > 0; off >>= 1)
        partial += __shfl_down_sync(0xffffffffu, partial, off, 16);
    if (lane == 0) counts[j] = partial;
    __syncthreads();

    if (tid == 0) {
        int best = 0, bc = counts[0];
        for (int jj = 1; jj < NMASK; jj++)
            if (counts[jj] > bc) { bc = counts[jj]; best = jj; }
        sbest = best;
        sflag = ((float)bc / (float)TOPK >= 0.3f) ? 1 : 0;
        s_inactive = 0;   // valid: if flag==0 every column is inactive
    }
    __syncthreads();

    const int best = sbest, flag = sflag;

    const int d0 = tid * 4;
    int act[4], s = 0;
#pragma unroll
    for (int q = 0; q < 4; q++) {
        int a = flag && mask_at(masks, mmode, (size_t)best * DDIM + d0 + q);
        act[q] = a;
        s += a;
        g_fmask[d0 + q] = a ? 1.0f : 0.0f;
    }
#pragma unroll
    for (int q = 0; q < 4; q++)
        if (!act[q]) { atomicMin(&s_inactive, d0 + q); break; }

    scan[tid] = s;
    __syncthreads();
#pragma unroll
    for (int off = 1; off < 1024; off <<= 1) {
        int v = (tid >= off) ? scan[tid - off] : 0;
        __syncthreads();
        scan[tid] += v;
        __syncthreads();
    }
    int pos = scan[tid] - s;
#pragma unroll
    for (int q = 0; q < 4; q++)
        if (act[q]) g_kidx[pos++] = d0 + q;
    __syncthreads();

    if (tid == 0) {
        int cnt = scan[1023];
        int kpad = (cnt + BK - 1) / BK * BK;
        int dummy = s_inactive;
        for (int q = cnt; q < kpad; q++) g_kidx[q] = dummy;
        g_kpad = kpad;
    }
}

// ---------------------------------------------------------------------------
// Kernels 3a/3b: gathered f32 -> (bf16 hi, bf16 lo) split conversion.
// ---------------------------------------------------------------------------
__device__ __forceinline__ unsigned short bf_bits(__nv_bfloat16 b) {
    unsigned short s; memcpy(&s, &b, 2); return s;
}
__device__ __forceinline__ void split4(float4 v, uint2& hi, uint2& lo) {
    __nv_bfloat16 h0 = __float2bfloat16(v.x), h1 = __float2bfloat16(v.y);
    __nv_bfloat16 h2 = __float2bfloat16(v.z), h3 = __float2bfloat16(v.w);
    __nv_bfloat16 l0 = __float2bfloat16(v.x - __bfloat162float(h0));
    __nv_bfloat16 l1 = __float2bfloat16(v.y - __bfloat162float(h1));
    __nv_bfloat16 l2 = __float2bfloat16(v.z - __bfloat162float(h2));
    __nv_bfloat16 l3 = __float2bfloat16(v.w - __bfloat162float(h3));
    hi.x = (uint32_t)bf_bits(h0) | ((uint32_t)bf_bits(h1) << 16);
    hi.y = (uint32_t)bf_bits(h2) | ((uint32_t)bf_bits(h3) << 16);
    lo.x = (uint32_t)bf_bits(l0) | ((uint32_t)bf_bits(l1) << 16);
    lo.y = (uint32_t)bf_bits(l2) | ((uint32_t)bf_bits(l3) << 16);
}

__global__ void convert_x_kernel(const float* __restrict__ x) {
    const int kpad = g_kpad;
    size_t i = (size_t)blockIdx.x * blockDim.x + threadIdx.x;
    int m = (int)(i >> 10);
    int jc = ((int)i & 1023) * 4;
    if (jc >= kpad) return;
    int k0 = g_kidx[jc], k1 = g_kidx[jc + 1];
    int k2 = g_kidx[jc + 2], k3 = g_kidx[jc + 3];
    const float* row = x + (size_t)m * DDIM;
    float4 v = make_float4(row[k0] * g_fmask[k0], row[k1] * g_fmask[k1],
                           row[k2] * g_fmask[k2], row[k3] * g_fmask[k3]);
    uint2 hi, lo;
    split4(v, hi, lo);
    size_t o = (size_t)m * DDIM + jc;
    *(uint2*)(g_Ah + o) = hi;
    *(uint2*)(g_Al + o) = lo;
}

__global__ void convert_w_kernel(const float* __restrict__ w) {
    const int kpad = g_kpad;
    size_t i = (size_t)blockIdx.x * blockDim.x + threadIdx.x;
    int n = (int)(i >> 10);
    int jc = ((int)i & 1023) * 4;
    if (jc >= kpad) return;
    int k0 = g_kidx[jc], k1 = g_kidx[jc + 1];
    int k2 = g_kidx[jc + 2], k3 = g_kidx[jc + 3];
    const float* row = w + (size_t)n * DDIM;
    float4 v = make_float4(row[k0], row[k1], row[k2], row[k3]);
    uint2 hi, lo;
    split4(v, hi, lo);
    size_t o = (size_t)n * DDIM + jc;
    *(uint2*)(g_Wh + o) = hi;
    *(uint2*)(g_Wl + o) = lo;
}

// ---------------------------------------------------------------------------
// Kernel 4: warp-MMA bf16x3 GEMM over compacted K (dynamic trip count).
// 128x128x32 CTA tile, 8 warps (2x4), warp tile 64x32, 3-stage cp.async,
// 2 CTAs/SM, register-lean inner loop (B per kk, A per mi-pair).
// ---------------------------------------------------------------------------
__global__ void __launch_bounds__(256, 2)
gemm_mma_kernel(float* __restrict__ C) {
    extern __shared__ char smem[];
    const uint32_t sb = smem_u32(smem);
    const int tid = threadIdx.x;
    const int wid = tid >> 5;
    const int lane = tid & 31;
    const int warp_m = wid & 1;
    const int warp_n = wid >> 1;

    const int m0 = blockIdx.y * BM;
    const int n0 = blockIdx.x * BN;
    const int NT = g_kpad / BK;          // dynamic k-tile count

    const int lr = tid >> 2;             // 0..63
    const int lch = tid & 3;             // 16B chunk
    const int lc = lch * 8;

    const __nv_bfloat16* srcp[4] = {
        g_Ah + (size_t)m0 * DDIM, g_Al + (size_t)m0 * DDIM,
        g_Wh + (size_t)n0 * DDIM, g_Wl + (size_t)n0 * DDIM};

#define LOAD_STAGE(base, kb)                                                   \
    do {                                                                       \
        _Pragma("unroll")                                                      \
        for (int t = 0; t < 4; t++) {                                          \
            const __nv_bfloat16* src = srcp[t] + (size_t)lr * DDIM + (kb) + lc; \
            uint32_t tb = (base) + t * TILE_B;                                 \
            cp16(tb + tile_off(lr, lch), src);                                 \
            cp16(tb + tile_off(lr + 64, lch), src + (size_t)64 * DDIM);        \
        }                                                                      \
    } while (0)

    // prologue: stages 0..STAGES-2 (guarded for short K)
#pragma unroll
    for (int it = 0; it < STAGES - 1; ++it) {
        if (it < NT) LOAD_STAGE(sb + it * STAGE_B, it * BK);
        cp_commit();
    }

    float acc[4][4][4];
#pragma unroll
    for (int mi = 0; mi < 4; mi++)
#pragma unroll
        for (int nj = 0; nj < 4; nj++)
#pragma unroll
            for (int q = 0; q < 4; q++) acc[mi][nj][q] = 0.0f;

    const int ar = warp_m * 64 + (lane & 15);
    const int br = warp_n * 32 + (lane & 15);
    const int kgrp = lane >> 4;

#pragma unroll 1
    for (int it = 0; it < NT; ++it) {
        cp_wait<STAGES - 2>();
        __syncthreads();   // stage(it) ready; all warps done with stage(it-1)

        if (it + STAGES - 1 < NT)
            LOAD_STAGE(sb + ((it + STAGES - 1) % STAGES) * STAGE_B,
                       (it + STAGES - 1) * BK);
        cp_commit();

        const uint32_t stg = sb + (it % STAGES) * STAGE_B;
#pragma unroll
        for (int kk = 0; kk < BK; kk += 16) {
            const int kch = (kk >> 3) + kgrp;
            uint32_t b_h[2][4], b_l[2][4];
#pragma unroll
            for (int ni = 0; ni < 2; ni++) {
                uint32_t off = tile_off(br + ni * 16, kch);
                ldsm4(b_h[ni], stg + 2 * TILE_B + off);
                ldsm4(b_l[ni], stg + 3 * TILE_B + off);
            }
            // two mi-pairs keep A-fragment live range small (reg budget 128)
#pragma unroll
            for (int mp = 0; mp < 2; mp++) {
                uint32_t a_h[2][4], a_l[2][4];
#pragma unroll
                for (int q = 0; q < 2; q++) {
                    uint32_t off = tile_off(ar + (mp * 2 + q) * 16, kch);
                    ldsm4(a_h[q], stg + off);
                    ldsm4(a_l[q], stg + TILE_B + off);
                }
#pragma unroll
                for (int q = 0; q < 2; q++) {
                    const int mi = mp * 2 + q;
#pragma unroll
                    for (int nj = 0; nj < 4; nj++) {
                        const int ni = nj >> 1, sub = nj & 1;
                        mma_bf16(acc[mi][nj], a_h[q], b_h[ni][sub], b_h[ni][sub + 2]);
                        mma_bf16(acc[mi][nj], a_l[q], b_h[ni][sub], b_h[ni][sub + 2]);
                        mma_bf16(acc[mi][nj], a_h[q], b_l[ni][sub], b_l[ni][sub + 2]);
                    }
                }
            }
        }
    }

    // epilogue: always write (zeros when gate is off / NT==0)
    const int crow = m0 + warp_m * 64 + (lane >> 2);
    const int ccol = n0 + warp_n * 32 + (lane & 3) * 2;
#pragma unroll
    for (int mi = 0; mi < 4; mi++) {
#pragma unroll
        for (int nj = 0; nj < 4; nj++) {
            float* p0 = C + (size_t)(crow + mi * 16) * NDIM + ccol + nj * 8;
            float* p1 = p0 + (size_t)8 * NDIM;
            *(float2*)p0 = make_float2(acc[mi][nj][0], acc[mi][nj][1]);
            *(float2*)p1 = make_float2(acc[mi][nj][2], acc[mi][nj][3]);
        }
    }
#undef LOAD_STAGE
}

// ---------------------------------------------------------------------------
// Launch
// ---------------------------------------------------------------------------
extern "C" void kernel_launch(void* const* d_in, const int* in_sizes, int n_in,
                              void* d_out, int out_size) {
    const float* x     = (const float*)d_in[0];
    const float* w     = (const float*)d_in[1];
    const void*  masks = d_in[2];
    const void*  perm  = d_in[3];
    float*       out   = (float*)d_out;

    cudaFuncSetAttribute(gemm_mma_kernel,
                         cudaFuncAttributeMaxDynamicSharedMemorySize, SMEM_TOTAL);

    detect_kernel<<<1, 256>>>(perm, masks);
    topk_kernel<<<DDIM / 256, 256>>>(x);
    select_kernel<<<1, 1024>>>(masks, perm);

    convert_x_kernel<<<(MDIM * 1024) / 256, 256>>>(x);
    convert_w_kernel<<<(NDIM * 1024) / 256, 256>>>(w);

    dim3 grid(NDIM / BN, MDIM / BM);   // (32, 32)
    gemm_mma_kernel<<<grid, 256, SMEM_TOTAL>>>(out);
}

// round 9
// speedup vs baseline: 3.0253x; 3.0253x over previous
#include <cuda_runtime.h>
#include <cuda_fp16.h>
#include <cstdint>
#include <cstring>

// Problem constants
#define DDIM   4096
#define TOPK   2048
#define NMASK  64
#define PBOUND 1024
#define MDIM   4096      // B*S
#define NDIM   4096      // O

// GEMM tiling: 128x128x32 fp16 single-term, 4-stage cp.async, 2 CTAs/SM
#define BM 128
#define BN 128
#define BK 32
#define STAGES 4
#define TILE_B (BM * BK * 2)           // 8192 bytes per fp16 tile (128 x 32)
#define STAGE_B (2 * TILE_B)           // A, W = 16384
#define SMEM_TOTAL (STAGES * STAGE_B)  // 65536 (x2 CTAs = 128KB < 228KB)

// ---------------------------------------------------------------------------
// Device-global scratch (allocation-free rule)
// ---------------------------------------------------------------------------
__device__ __align__(16) float g_fmask[DDIM];
__device__ unsigned char g_topk[DDIM];
__device__ int g_perm_mode;     // 8 = int64 storage, 4 = int32
__device__ int g_mask_mode;     // 1 = uint8, 4 = int32, 5 = float32
__device__ int g_kidx[DDIM];    // compacted active K indices (sorted) + padding
__device__ int g_kpad;          // active count padded to multiple of BK
__device__ __align__(16) __half g_Af[(size_t)MDIM * DDIM];
__device__ __align__(16) __half g_Wf[(size_t)NDIM * DDIM];

// ---------------------------------------------------------------------------
// PTX helpers (baseline sm_80+ features only)
// ---------------------------------------------------------------------------
__device__ __forceinline__ uint32_t smem_u32(const void* p) {
    uint32_t a;
    asm("{ .reg .u64 t; cvta.to.shared.u64 t, %1; cvt.u32.u64 %0, t; }"
        : "=r"(a) : "l"(p));
    return a;
}
__device__ __forceinline__ void cp16(uint32_t dst, const void* src) {
    asm volatile("cp.async.cg.shared.global [%0], [%1], 16;"
                 :: "r"(dst), "l"(src) : "memory");
}
__device__ __forceinline__ void cp_commit() {
    asm volatile("cp.async.commit_group;" ::: "memory");
}
template <int N>
__device__ __forceinline__ void cp_wait() {
    asm volatile("cp.async.wait_group %0;" :: "n"(N) : "memory");
}
__device__ __forceinline__ void ldsm4(uint32_t* r, uint32_t addr) {
    asm volatile("ldmatrix.sync.aligned.m8n8.x4.shared.b16 {%0,%1,%2,%3}, [%4];"
                 : "=r"(r[0]), "=r"(r[1]), "=r"(r[2]), "=r"(r[3]) : "r"(addr));
}
__device__ __forceinline__ void mma_f16(float* c, const uint32_t* a,
                                        uint32_t b0, uint32_t b1) {
    asm volatile(
        "mma.sync.aligned.m16n8k16.row.col.f32.f16.f16.f32 "
        "{%0,%1,%2,%3}, {%4,%5,%6,%7}, {%8,%9}, {%0,%1,%2,%3};"
        : "+f"(c[0]), "+f"(c[1]), "+f"(c[2]), "+f"(c[3])
        : "r"(a[0]), "r"(a[1]), "r"(a[2]), "r"(a[3]), "r"(b0), "r"(b1));
}
// Swizzled byte offset inside a 128x32-fp16 tile (64B rows, 4x16B chunks).
__device__ __forceinline__ uint32_t tile_off(int row, int chunk) {
    return (uint32_t)row * 64u + (uint32_t)((chunk ^ ((row >> 1) & 3)) * 16);
}

// ---------------------------------------------------------------------------
// Kernel 0: dtype detection (deterministic), parallel
// ---------------------------------------------------------------------------
__global__ void detect_kernel(const void* __restrict__ perm,
                              const void* __restrict__ masks) {
    __shared__ int s_zero[8], s_f32[8];
    __shared__ unsigned int s_max[8];
    int tid = threadIdx.x, wid = tid >> 5, lane = tid & 31;

    const int* p32 = (const int*)perm;
    int zeros = 0;
    for (int i = 1 + 2 * tid; i < 4096; i += 512) zeros += (p32[i] == 0);

    const unsigned int* m32 = (const unsigned int*)masks;
    int has_f32 = 0;
    unsigned int maxv = 0;
    for (int i = tid; i < 1024; i += 256) {
        unsigned int v = m32[i];
        if (v == 0x3F800000u) has_f32 = 1;
        if (v > maxv) maxv = v;
    }
#pragma unroll
    for (int off = 16; off > 0; off >>= 1) {
        zeros   += __shfl_down_sync(0xffffffffu, zeros, off);
        has_f32 |= __shfl_down_sync(0xffffffffu, has_f32, off);
        unsigned int o = __shfl_down_sync(0xffffffffu, maxv, off);
        if (o > maxv) maxv = o;
    }
    if (lane == 0) { s_zero[wid] = zeros; s_f32[wid] = has_f32; s_max[wid] = maxv; }
    __syncthreads();
    if (tid == 0) {
        int z = 0, f = 0;
        unsigned int mx = 0;
        for (int i = 0; i < 8; i++) {
            z += s_zero[i];
            f |= s_f32[i];
            if (s_max[i] > mx) mx = s_max[i];
        }
        g_perm_mode = (z >= 1000) ? 8 : 4;
        g_mask_mode = f ? 5 : (mx <= 1u ? 4 : 1);
    }
}

__device__ __forceinline__ int mask_at(const void* masks, int mode, size_t idx) {
    if (mode == 1) return ((const unsigned char*)masks)[idx] != 0;
    if (mode == 4) return ((const int*)masks)[idx] != 0;
    return ((const float*)masks)[idx] != 0.0f;
}

// ---------------------------------------------------------------------------
// Kernel 1: exact top-k membership by rank counting
// ---------------------------------------------------------------------------
__global__ void topk_kernel(const float* __restrict__ x) {
    __shared__ float a[DDIM];
    const float* f0 = x + (size_t)PBOUND * DDIM;
    for (int i = threadIdx.x; i < DDIM; i += blockDim.x) a[i] = fabsf(f0[i]);
    __syncthreads();

    int d = blockIdx.x * blockDim.x + threadIdx.x;
    float ad = a[d];
    int cnt = 0;
#pragma unroll 8
    for (int e = 0; e < DDIM; e++) {
        float ae = a[e];
        cnt += (int)((ae > ad) || (ae == ad && e < d));
    }
    g_topk[d] = (cnt < TOPK) ? 1u : 0u;
}

// ---------------------------------------------------------------------------
// Kernel 2: mask selection + gate -> g_fmask, plus K compaction -> g_kidx/kpad
// ---------------------------------------------------------------------------
__global__ void select_kernel(const void* __restrict__ masks,
                              const void* __restrict__ perm) {
    __shared__ int counts[NMASK];
    __shared__ int sbest, sflag;
    __shared__ int scan[1024];
    __shared__ int s_inactive;

    int pmode = g_perm_mode, mmode = g_mask_mode;
    int tid = threadIdx.x, j = tid >> 4, lane = tid & 15;

    int partial = 0;
    for (int d = lane; d < DDIM; d += 16) {
        if (g_topk[d]) {
            int p = (pmode == 8) ? (int)((const long long*)perm)[d]
                                 : ((const int*)perm)[d];
            partial += mask_at(masks, mmode, (size_t)j * DDIM + p);
        }
    }
#pragma unroll
    for (int off = 8; off > 0; off >>= 1)
        partial += __shfl_down_sync(0xffffffffu, partial, off, 16);
    if (lane == 0) counts[j] = partial;
    __syncthreads();

    if (tid == 0) {
        int best = 0, bc = counts[0];
        for (int jj = 1; jj < NMASK; jj++)
            if (counts[jj] > bc) { bc = counts[jj]; best = jj; }
        sbest = best;
        sflag = ((float)bc / (float)TOPK >= 0.3f) ? 1 : 0;
        s_inactive = 0;   // valid: if flag==0 every column is inactive
    }
    __syncthreads();

    const int best = sbest, flag = sflag;

    const int d0 = tid * 4;
    int act[4], s = 0;
#pragma unroll
    for (int q = 0; q < 4; q++) {
        int a = flag && mask_at(masks, mmode, (size_t)best * DDIM + d0 + q);
        act[q] = a;
        s += a;
        g_fmask[d0 + q] = a ? 1.0f : 0.0f;
    }
#pragma unroll
    for (int q = 0; q < 4; q++)
        if (!act[q]) { atomicMin(&s_inactive, d0 + q); break; }

    scan[tid] = s;
    __syncthreads();
#pragma unroll
    for (int off = 1; off < 1024; off <<= 1) {
        int v = (tid >= off) ? scan[tid - off] : 0;
        __syncthreads();
        scan[tid] += v;
        __syncthreads();
    }
    int pos = scan[tid] - s;
#pragma unroll
    for (int q = 0; q < 4; q++)
        if (act[q]) g_kidx[pos++] = d0 + q;
    __syncthreads();

    if (tid == 0) {
        int cnt = scan[1023];
        int kpad = (cnt + BK - 1) / BK * BK;
        int dummy = s_inactive;
        for (int q = cnt; q < kpad; q++) g_kidx[q] = dummy;
        g_kpad = kpad;
    }
}

// ---------------------------------------------------------------------------
// Kernels 3a/3b: gathered f32 -> fp16 conversion (compacted K layout).
// ---------------------------------------------------------------------------
__device__ __forceinline__ uint32_t pack_half2(float a, float b) {
    __half2 h = __floats2half2_rn(a, b);
    uint32_t u; memcpy(&u, &h, 4); return u;
}

__global__ void convert_x_kernel(const float* __restrict__ x) {
    const int kpad = g_kpad;
    size_t i = (size_t)blockIdx.x * blockDim.x + threadIdx.x;
    int m = (int)(i >> 10);
    int jc = ((int)i & 1023) * 4;
    if (jc >= kpad) return;
    int k0 = g_kidx[jc], k1 = g_kidx[jc + 1];
    int k2 = g_kidx[jc + 2], k3 = g_kidx[jc + 3];
    const float* row = x + (size_t)m * DDIM;
    uint2 v;
    v.x = pack_half2(row[k0] * g_fmask[k0], row[k1] * g_fmask[k1]);
    v.y = pack_half2(row[k2] * g_fmask[k2], row[k3] * g_fmask[k3]);
    *(uint2*)(g_Af + (size_t)m * DDIM + jc) = v;
}

__global__ void convert_w_kernel(const float* __restrict__ w) {
    const int kpad = g_kpad;
    size_t i = (size_t)blockIdx.x * blockDim.x + threadIdx.x;
    int n = (int)(i >> 10);
    int jc = ((int)i & 1023) * 4;
    if (jc >= kpad) return;
    int k0 = g_kidx[jc], k1 = g_kidx[jc + 1];
    int k2 = g_kidx[jc + 2], k3 = g_kidx[jc + 3];
    const float* row = w + (size_t)n * DDIM;
    uint2 v;
    v.x = pack_half2(row[k0], row[k1]);
    v.y = pack_half2(row[k2], row[k3]);
    *(uint2*)(g_Wf + (size_t)n * DDIM + jc) = v;
}

// ---------------------------------------------------------------------------
// Kernel 4: warp-MMA fp16 single-term GEMM over compacted K.
// 128x128x32 CTA tile, 8 warps (2x4), warp tile 64x32, 4-stage cp.async,
// 2 CTAs/SM.
// ---------------------------------------------------------------------------
__global__ void __launch_bounds__(256, 2)
gemm_mma_kernel(float* __restrict__ C) {
    extern __shared__ char smem[];
    const uint32_t sb = smem_u32(smem);
    const int tid = threadIdx.x;
    const int wid = tid >> 5;
    const int lane = tid & 31;
    const int warp_m = wid & 1;
    const int warp_n = wid >> 1;

    const int m0 = blockIdx.y * BM;
    const int n0 = blockIdx.x * BN;
    const int NT = g_kpad / BK;          // dynamic k-tile count

    const int lr = tid >> 2;             // 0..63
    const int lch = tid & 3;             // 16B chunk
    const int lc = lch * 8;

    const __half* A = g_Af + (size_t)m0 * DDIM;
    const __half* W = g_Wf + (size_t)n0 * DDIM;

#define LOAD_STAGE(base, kb)                                                   \
    do {                                                                       \
        const __half* sa = A + (size_t)lr * DDIM + (kb) + lc;                  \
        const __half* sw = W + (size_t)lr * DDIM + (kb) + lc;                  \
        cp16((base) + tile_off(lr, lch), sa);                                  \
        cp16((base) + tile_off(lr + 64, lch), sa + (size_t)64 * DDIM);         \
        cp16((base) + TILE_B + tile_off(lr, lch), sw);                         \
        cp16((base) + TILE_B + tile_off(lr + 64, lch), sw + (size_t)64 * DDIM);\
    } while (0)

    // prologue: stages 0..STAGES-2 (guarded for short K)
#pragma unroll
    for (int it = 0; it < STAGES - 1; ++it) {
        if (it < NT) LOAD_STAGE(sb + it * STAGE_B, it * BK);
        cp_commit();
    }

    float acc[4][4][4];
#pragma unroll
    for (int mi = 0; mi < 4; mi++)
#pragma unroll
        for (int nj = 0; nj < 4; nj++)
#pragma unroll
            for (int q = 0; q < 4; q++) acc[mi][nj][q] = 0.0f;

    const int ar = warp_m * 64 + (lane & 15);
    const int br = warp_n * 32 + (lane & 15);
    const int kgrp = lane >> 4;

#pragma unroll 1
    for (int it = 0; it < NT; ++it) {
        cp_wait<STAGES - 2>();
        __syncthreads();   // stage(it) ready; all warps done with old buffer

        if (it + STAGES - 1 < NT)
            LOAD_STAGE(sb + ((it + STAGES - 1) & (STAGES - 1)) * STAGE_B,
                       (it + STAGES - 1) * BK);
        cp_commit();

        const uint32_t stg = sb + (it & (STAGES - 1)) * STAGE_B;
#pragma unroll
        for (int kk = 0; kk < BK; kk += 16) {
            const int kch = (kk >> 3) + kgrp;
            uint32_t af[4][4], bf[2][4];
#pragma unroll
            for (int ni = 0; ni < 2; ni++)
                ldsm4(bf[ni], stg + TILE_B + tile_off(br + ni * 16, kch));
#pragma unroll
            for (int mi = 0; mi < 4; mi++)
                ldsm4(af[mi], stg + tile_off(ar + mi * 16, kch));
#pragma unroll
            for (int mi = 0; mi < 4; mi++) {
#pragma unroll
                for (int nj = 0; nj < 4; nj++) {
                    const int ni = nj >> 1, sub = nj & 1;
                    mma_f16(acc[mi][nj], af[mi], bf[ni][sub], bf[ni][sub + 2]);
                }
            }
        }
    }

    // epilogue: always write (zeros when gate is off / NT==0)
    const int crow = m0 + warp_m * 64 + (lane >> 2);
    const int ccol = n0 + warp_n * 32 + (lane & 3) * 2;
#pragma unroll
    for (int mi = 0; mi < 4; mi++) {
#pragma unroll
        for (int nj = 0; nj < 4; nj++) {
            float* p0 = C + (size_t)(crow + mi * 16) * NDIM + ccol + nj * 8;
            float* p1 = p0 + (size_t)8 * NDIM;
            *(float2*)p0 = make_float2(acc[mi][nj][0], acc[mi][nj][1]);
            *(float2*)p1 = make_float2(acc[mi][nj][2], acc[mi][nj][3]);
        }
    }
#undef LOAD_STAGE
}

// ---------------------------------------------------------------------------
// Launch
// ---------------------------------------------------------------------------
extern "C" void kernel_launch(void* const* d_in, const int* in_sizes, int n_in,
                              void* d_out, int out_size) {
    const float* x     = (const float*)d_in[0];
    const float* w     = (const float*)d_in[1];
    const void*  masks = d_in[2];
    const void*  perm  = d_in[3];
    float*       out   = (float*)d_out;

    cudaFuncSetAttribute(gemm_mma_kernel,
                         cudaFuncAttributeMaxDynamicSharedMemorySize, SMEM_TOTAL);

    detect_kernel<<<1, 256>>>(perm, masks);
    topk_kernel<<<DDIM / 256, 256>>>(x);
    select_kernel<<<1, 1024>>>(masks, perm);

    convert_x_kernel<<<(MDIM * 1024) / 256, 256>>>(x);
    convert_w_kernel<<<(NDIM * 1024) / 256, 256>>>(w);

    dim3 grid(NDIM / BN, MDIM / BM);   // (32, 32)
    gemm_mma_kernel<<<grid, 256, SMEM_TOTAL>>>(out);
}

// round 10
// speedup vs baseline: 3.0442x; 1.0062x over previous
#include <cuda_runtime.h>
#include <cuda_fp16.h>
#include <cstdint>
#include <cstring>

// Problem constants
#define DDIM   4096
#define TOPK   2048
#define NMASK  64
#define PBOUND 1024
#define MDIM   4096      // B*S
#define NDIM   4096      // O

// GEMM tiling: 128x128x32 fp16 single-term, 4-stage cp.async, 2 CTAs/SM
#define BM 128
#define BN 128
#define BK 32
#define STAGES 4
#define TILE_B (BM * BK * 2)           // 8192 bytes per fp16 tile (128 x 32)
#define STAGE_B (2 * TILE_B)           // A, W = 16384
#define SMEM_TOTAL (STAGES * STAGE_B)  // 65536 (x2 CTAs = 128KB < 228KB)

// ---------------------------------------------------------------------------
// Device-global scratch (allocation-free rule)
// ---------------------------------------------------------------------------
__device__ __align__(16) float g_fmask[DDIM];
__device__ unsigned char g_topk[DDIM];
__device__ int g_perm_mode;     // 8 = int64 storage, 4 = int32
__device__ int g_mask_mode;     // 1 = uint8, 4 = int32, 5 = float32
__device__ int g_kidx[DDIM];    // compacted active K indices (sorted) + padding
__device__ int g_kpad;          // active count padded to multiple of BK
__device__ __align__(16) __half g_Af[(size_t)MDIM * DDIM];
__device__ __align__(16) __half g_Wf[(size_t)NDIM * DDIM];

// ---------------------------------------------------------------------------
// PTX helpers (baseline sm_80+ features only)
// ---------------------------------------------------------------------------
__device__ __forceinline__ uint32_t smem_u32(const void* p) {
    uint32_t a;
    asm("{ .reg .u64 t; cvta.to.shared.u64 t, %1; cvt.u32.u64 %0, t; }"
        : "=r"(a) : "l"(p));
    return a;
}
__device__ __forceinline__ void cp16(uint32_t dst, const void* src) {
    asm volatile("cp.async.cg.shared.global [%0], [%1], 16;"
                 :: "r"(dst), "l"(src) : "memory");
}
__device__ __forceinline__ void cp_commit() {
    asm volatile("cp.async.commit_group;" ::: "memory");
}
template <int N>
__device__ __forceinline__ void cp_wait() {
    asm volatile("cp.async.wait_group %0;" :: "n"(N) : "memory");
}
__device__ __forceinline__ void ldsm4(uint32_t* r, uint32_t addr) {
    asm volatile("ldmatrix.sync.aligned.m8n8.x4.shared.b16 {%0,%1,%2,%3}, [%4];"
                 : "=r"(r[0]), "=r"(r[1]), "=r"(r[2]), "=r"(r[3]) : "r"(addr));
}
__device__ __forceinline__ void mma_f16(float* c, const uint32_t* a,
                                        uint32_t b0, uint32_t b1) {
    asm volatile(
        "mma.sync.aligned.m16n8k16.row.col.f32.f16.f16.f32 "
        "{%0,%1,%2,%3}, {%4,%5,%6,%7}, {%8,%9}, {%0,%1,%2,%3};"
        : "+f"(c[0]), "+f"(c[1]), "+f"(c[2]), "+f"(c[3])
        : "r"(a[0]), "r"(a[1]), "r"(a[2]), "r"(a[3]), "r"(b0), "r"(b1));
}
// Swizzled byte offset inside a 128x32-fp16 tile (64B rows, 4x16B chunks).
__device__ __forceinline__ uint32_t tile_off(int row, int chunk) {
    return (uint32_t)row * 64u + (uint32_t)((chunk ^ ((row >> 1) & 3)) * 16);
}

__device__ __forceinline__ int mask_at(const void* masks, int mode, size_t idx) {
    if (mode == 1) return ((const unsigned char*)masks)[idx] != 0;
    if (mode == 4) return ((const int*)masks)[idx] != 0;
    return ((const float*)masks)[idx] != 0.0f;
}

// ---------------------------------------------------------------------------
// Kernel 1 (merged): blocks 0..15 = top-k rank counting; block 16 = dtype
// detection. Both deterministic and independent.
// ---------------------------------------------------------------------------
__global__ void prep_kernel(const float* __restrict__ x,
                            const void* __restrict__ perm,
                            const void* __restrict__ masks) {
    __shared__ float a[DDIM];   // used by top-k blocks only (16KB)
    int tid = threadIdx.x;

    if (blockIdx.x < 16) {
        const float* f0 = x + (size_t)PBOUND * DDIM;
        for (int i = tid; i < DDIM; i += blockDim.x) a[i] = fabsf(f0[i]);
        __syncthreads();

        int d = blockIdx.x * blockDim.x + tid;
        float ad = a[d];
        int cnt = 0;
#pragma unroll 8
        for (int e = 0; e < DDIM; e++) {
            float ae = a[e];
            cnt += (int)((ae > ad) || (ae == ad && e < d));
        }
        g_topk[d] = (cnt < TOPK) ? 1u : 0u;
    } else {
        // dtype detection (256 threads)
        __shared__ int s_zero[8], s_f32[8];
        __shared__ unsigned int s_max[8];
        int wid = tid >> 5, lane = tid & 31;

        const int* p32 = (const int*)perm;
        int zeros = 0;
        for (int i = 1 + 2 * tid; i < 4096; i += 512) zeros += (p32[i] == 0);

        const unsigned int* m32 = (const unsigned int*)masks;
        int has_f32 = 0;
        unsigned int maxv = 0;
        for (int i = tid; i < 1024; i += 256) {
            unsigned int v = m32[i];
            if (v == 0x3F800000u) has_f32 = 1;
            if (v > maxv) maxv = v;
        }
#pragma unroll
        for (int off = 16; off > 0; off >>= 1) {
            zeros   += __shfl_down_sync(0xffffffffu, zeros, off);
            has_f32 |= __shfl_down_sync(0xffffffffu, has_f32, off);
            unsigned int o = __shfl_down_sync(0xffffffffu, maxv, off);
            if (o > maxv) maxv = o;
        }
        if (lane == 0) { s_zero[wid] = zeros; s_f32[wid] = has_f32; s_max[wid] = maxv; }
        __syncthreads();
        if (tid == 0) {
            int z = 0, f = 0;
            unsigned int mx = 0;
            for (int i = 0; i < 8; i++) {
                z += s_zero[i];
                f |= s_f32[i];
                if (s_max[i] > mx) mx = s_max[i];
            }
            g_perm_mode = (z >= 1000) ? 8 : 4;
            g_mask_mode = f ? 5 : (mx <= 1u ? 4 : 1);
        }
    }
}

// ---------------------------------------------------------------------------
// Kernel 2: mask selection + gate -> g_fmask, plus K compaction -> g_kidx/kpad
// ---------------------------------------------------------------------------
__global__ void select_kernel(const void* __restrict__ masks,
                              const void* __restrict__ perm) {
    __shared__ int counts[NMASK];
    __shared__ int sbest, sflag;
    __shared__ int scan[1024];
    __shared__ int s_inactive;

    int pmode = g_perm_mode, mmode = g_mask_mode;
    int tid = threadIdx.x, j = tid >> 4, lane = tid & 15;

    int partial = 0;
    for (int d = lane; d < DDIM; d += 16) {
        if (g_topk[d]) {
            int p = (pmode == 8) ? (int)((const long long*)perm)[d]
                                 : ((const int*)perm)[d];
            partial += mask_at(masks, mmode, (size_t)j * DDIM + p);
        }
    }
#pragma unroll
    for (int off = 8; off > 0; off >>= 1)
        partial += __shfl_down_sync(0xffffffffu, partial, off, 16);
    if (lane == 0) counts[j] = partial;
    __syncthreads();

    if (tid == 0) {
        int best = 0, bc = counts[0];
        for (int jj = 1; jj < NMASK; jj++)
            if (counts[jj] > bc) { bc = counts[jj]; best = jj; }
        sbest = best;
        sflag = ((float)bc / (float)TOPK >= 0.3f) ? 1 : 0;
        s_inactive = 0;   // valid: if flag==0 every column is inactive
    }
    __syncthreads();

    const int best = sbest, flag = sflag;

    const int d0 = tid * 4;
    int act[4], s = 0;
#pragma unroll
    for (int q = 0; q < 4; q++) {
        int a = flag && mask_at(masks, mmode, (size_t)best * DDIM + d0 + q);
        act[q] = a;
        s += a;
        g_fmask[d0 + q] = a ? 1.0f : 0.0f;
    }
#pragma unroll
    for (int q = 0; q < 4; q++)
        if (!act[q]) { atomicMin(&s_inactive, d0 + q); break; }

    scan[tid] = s;
    __syncthreads();
#pragma unroll
    for (int off = 1; off < 1024; off <<= 1) {
        int v = (tid >= off) ? scan[tid - off] : 0;
        __syncthreads();
        scan[tid] += v;
        __syncthreads();
    }
    int pos = scan[tid] - s;
#pragma unroll
    for (int q = 0; q < 4; q++)
        if (act[q]) g_kidx[pos++] = d0 + q;
    __syncthreads();

    if (tid == 0) {
        int cnt = scan[1023];
        int kpad = (cnt + BK - 1) / BK * BK;
        int dummy = s_inactive;
        for (int q = cnt; q < kpad; q++) g_kidx[q] = dummy;
        g_kpad = kpad;
    }
}

// ---------------------------------------------------------------------------
// Kernel 3 (merged): gathered f32 -> fp16 conversion for BOTH X and W.
// row_id < MDIM: X (masked); else W. Compacted-K layout.
// ---------------------------------------------------------------------------
__device__ __forceinline__ uint32_t pack_half2(float a, float b) {
    __half2 h = __floats2half2_rn(a, b);
    uint32_t u; memcpy(&u, &h, 4); return u;
}

__global__ void convert_kernel(const float* __restrict__ x,
                               const float* __restrict__ w) {
    const int kpad = g_kpad;
    size_t i = (size_t)blockIdx.x * blockDim.x + threadIdx.x;
    int row_id = (int)(i >> 10);        // 0..(MDIM+NDIM-1)
    int jc = ((int)i & 1023) * 4;
    if (jc >= kpad) return;
    int k0 = g_kidx[jc], k1 = g_kidx[jc + 1];
    int k2 = g_kidx[jc + 2], k3 = g_kidx[jc + 3];

    uint2 v;
    if (row_id < MDIM) {
        const float* row = x + (size_t)row_id * DDIM;
        v.x = pack_half2(row[k0] * g_fmask[k0], row[k1] * g_fmask[k1]);
        v.y = pack_half2(row[k2] * g_fmask[k2], row[k3] * g_fmask[k3]);
        *(uint2*)(g_Af + (size_t)row_id * DDIM + jc) = v;
    } else {
        const float* row = w + (size_t)(row_id - MDIM) * DDIM;
        v.x = pack_half2(row[k0], row[k1]);
        v.y = pack_half2(row[k2], row[k3]);
        *(uint2*)(g_Wf + (size_t)(row_id - MDIM) * DDIM + jc) = v;
    }
}

// ---------------------------------------------------------------------------
// Kernel 4: warp-MMA fp16 single-term GEMM over compacted K.
// 128x128x32 CTA tile, 8 warps (2x4), warp tile 64x32, 4-stage cp.async,
// 2 CTAs/SM. B fragments for the whole BK tile hoisted (latency hiding).
// ---------------------------------------------------------------------------
__global__ void __launch_bounds__(256, 2)
gemm_mma_kernel(float* __restrict__ C) {
    extern __shared__ char smem[];
    const uint32_t sb = smem_u32(smem);
    const int tid = threadIdx.x;
    const int wid = tid >> 5;
    const int lane = tid & 31;
    const int warp_m = wid & 1;
    const int warp_n = wid >> 1;

    const int m0 = blockIdx.y * BM;
    const int n0 = blockIdx.x * BN;
    const int NT = g_kpad / BK;          // dynamic k-tile count

    const int lr = tid >> 2;             // 0..63
    const int lch = tid & 3;             // 16B chunk
    const int lc = lch * 8;

    const __half* A = g_Af + (size_t)m0 * DDIM;
    const __half* W = g_Wf + (size_t)n0 * DDIM;

#define LOAD_STAGE(base, kb)                                                   \
    do {                                                                       \
        const __half* sa = A + (size_t)lr * DDIM + (kb) + lc;                  \
        const __half* sw = W + (size_t)lr * DDIM + (kb) + lc;                  \
        cp16((base) + tile_off(lr, lch), sa);                                  \
        cp16((base) + tile_off(lr + 64, lch), sa + (size_t)64 * DDIM);         \
        cp16((base) + TILE_B + tile_off(lr, lch), sw);                         \
        cp16((base) + TILE_B + tile_off(lr + 64, lch), sw + (size_t)64 * DDIM);\
    } while (0)

    // prologue: stages 0..STAGES-2 (guarded for short K)
#pragma unroll
    for (int it = 0; it < STAGES - 1; ++it) {
        if (it < NT) LOAD_STAGE(sb + it * STAGE_B, it * BK);
        cp_commit();
    }

    float acc[4][4][4];
#pragma unroll
    for (int mi = 0; mi < 4; mi++)
#pragma unroll
        for (int nj = 0; nj < 4; nj++)
#pragma unroll
            for (int q = 0; q < 4; q++) acc[mi][nj][q] = 0.0f;

    const int ar = warp_m * 64 + (lane & 15);
    const int br = warp_n * 32 + (lane & 15);
    const int kgrp = lane >> 4;

#pragma unroll 1
    for (int it = 0; it < NT; ++it) {
        cp_wait<STAGES - 2>();
        __syncthreads();   // stage(it) ready; all warps done with old buffer

        if (it + STAGES - 1 < NT)
            LOAD_STAGE(sb + ((it + STAGES - 1) & (STAGES - 1)) * STAGE_B,
                       (it + STAGES - 1) * BK);
        cp_commit();

        const uint32_t stg = sb + (it & (STAGES - 1)) * STAGE_B;

        // hoist ALL B fragments for this 32-K tile (4 x ldsm4 = 16 regs)
        uint32_t bfr[4][4];
#pragma unroll
        for (int g = 0; g < 2; g++)
#pragma unroll
            for (int ni = 0; ni < 2; ni++)
                ldsm4(bfr[g * 2 + ni],
                      stg + TILE_B + tile_off(br + ni * 16, g * 2 + kgrp));

#pragma unroll
        for (int g = 0; g < 2; g++) {
            const int kch = g * 2 + kgrp;
            uint32_t af[4][4];
#pragma unroll
            for (int mi = 0; mi < 4; mi++)
                ldsm4(af[mi], stg + tile_off(ar + mi * 16, kch));
#pragma unroll
            for (int mi = 0; mi < 4; mi++) {
#pragma unroll
                for (int nj = 0; nj < 4; nj++) {
                    const int ni = nj >> 1, sub = nj & 1;
                    mma_f16(acc[mi][nj], af[mi],
                            bfr[g * 2 + ni][sub], bfr[g * 2 + ni][sub + 2]);
                }
            }
        }
    }

    // epilogue: always write (zeros when gate is off / NT==0)
    const int crow = m0 + warp_m * 64 + (lane >> 2);
    const int ccol = n0 + warp_n * 32 + (lane & 3) * 2;
#pragma unroll
    for (int mi = 0; mi < 4; mi++) {
#pragma unroll
        for (int nj = 0; nj < 4; nj++) {
            float* p0 = C + (size_t)(crow + mi * 16) * NDIM + ccol + nj * 8;
            float* p1 = p0 + (size_t)8 * NDIM;
            *(float2*)p0 = make_float2(acc[mi][nj][0], acc[mi][nj][1]);
            *(float2*)p1 = make_float2(acc[mi][nj][2], acc[mi][nj][3]);
        }
    }
#undef LOAD_STAGE
}

// ---------------------------------------------------------------------------
// Launch
// ---------------------------------------------------------------------------
extern "C" void kernel_launch(void* const* d_in, const int* in_sizes, int n_in,
                              void* d_out, int out_size) {
    const float* x     = (const float*)d_in[0];
    const float* w     = (const float*)d_in[1];
    const void*  masks = d_in[2];
    const void*  perm  = d_in[3];
    float*       out   = (float*)d_out;

    cudaFuncSetAttribute(gemm_mma_kernel,
                         cudaFuncAttributeMaxDynamicSharedMemorySize, SMEM_TOTAL);

    prep_kernel<<<17, 256>>>(x, perm, masks);           // topk (0-15) + detect (16)
    select_kernel<<<1, 1024>>>(masks, perm);
    convert_kernel<<<((MDIM + NDIM) * 1024) / 256, 256>>>(x, w);

    dim3 grid(NDIM / BN, MDIM / BM);   // (32, 32)
    gemm_mma_kernel<<<grid, 256, SMEM_TOTAL>>>(out);
}

// round 11
// speedup vs baseline: 4.1421x; 1.3606x over previous
#include <cuda_runtime.h>
#include <cuda_fp16.h>
#include <cstdint>
#include <cstring>

// Problem constants
#define DDIM   4096
#define TOPK   2048
#define NMASK  64
#define PBOUND 1024
#define MDIM   4096      // B*S
#define NDIM   4096      // O

// GEMM tiling: 128x128x32 fp16 single-term, 4-stage cp.async, 2 CTAs/SM
#define BM 128
#define BN 128
#define BK 32
#define STAGES 4
#define TILE_B (BM * BK * 2)           // 8192 bytes per fp16 tile (128 x 32)
#define STAGE_B (2 * TILE_B)           // A, W = 16384
#define SMEM_TOTAL (STAGES * STAGE_B)  // 65536 (x2 CTAs = 128KB < 228KB)

// ---------------------------------------------------------------------------
// Device-global scratch (allocation-free rule)
// ---------------------------------------------------------------------------
__device__ int g_pcnt[4 * DDIM];        // partial rank counts (4 e-ranges)
__device__ int g_perm_mode;             // 8 = int64 storage, 4 = int32
__device__ int g_mask_mode;             // 1 = uint8, 4 = int32, 5 = float32
__device__ __align__(16) int g_kidx[DDIM];  // compacted active K indices
__device__ int g_kpad;                  // active count padded to BK
__device__ int g_kcnt;                  // exact active count
__device__ __align__(16) __half g_Af[(size_t)MDIM * DDIM];
__device__ __align__(16) __half g_Wf[(size_t)NDIM * DDIM];

// ---------------------------------------------------------------------------
// PTX helpers (baseline sm_80+ features only)
// ---------------------------------------------------------------------------
__device__ __forceinline__ uint32_t smem_u32(const void* p) {
    uint32_t a;
    asm("{ .reg .u64 t; cvta.to.shared.u64 t, %1; cvt.u32.u64 %0, t; }"
        : "=r"(a) : "l"(p));
    return a;
}
__device__ __forceinline__ void cp16(uint32_t dst, const void* src) {
    asm volatile("cp.async.cg.shared.global [%0], [%1], 16;"
                 :: "r"(dst), "l"(src) : "memory");
}
__device__ __forceinline__ void cp_commit() {
    asm volatile("cp.async.commit_group;" ::: "memory");
}
template <int N>
__device__ __forceinline__ void cp_wait() {
    asm volatile("cp.async.wait_group %0;" :: "n"(N) : "memory");
}
__device__ __forceinline__ void ldsm4(uint32_t* r, uint32_t addr) {
    asm volatile("ldmatrix.sync.aligned.m8n8.x4.shared.b16 {%0,%1,%2,%3}, [%4];"
                 : "=r"(r[0]), "=r"(r[1]), "=r"(r[2]), "=r"(r[3]) : "r"(addr));
}
__device__ __forceinline__ void mma_f16(float* c, const uint32_t* a,
                                        uint32_t b0, uint32_t b1) {
    asm volatile(
        "mma.sync.aligned.m16n8k16.row.col.f32.f16.f16.f32 "
        "{%0,%1,%2,%3}, {%4,%5,%6,%7}, {%8,%9}, {%0,%1,%2,%3};"
        : "+f"(c[0]), "+f"(c[1]), "+f"(c[2]), "+f"(c[3])
        : "r"(a[0]), "r"(a[1]), "r"(a[2]), "r"(a[3]), "r"(b0), "r"(b1));
}
// Swizzled byte offset inside a 128x32-fp16 tile (64B rows, 4x16B chunks).
__device__ __forceinline__ uint32_t tile_off(int row, int chunk) {
    return (uint32_t)row * 64u + (uint32_t)((chunk ^ ((row >> 1) & 3)) * 16);
}

__device__ __forceinline__ int mask_at(const void* masks, int mode, size_t idx) {
    if (mode == 1) return ((const unsigned char*)masks)[idx] != 0;
    if (mode == 4) return ((const int*)masks)[idx] != 0;
    return ((const float*)masks)[idx] != 0.0f;
}

// ---------------------------------------------------------------------------
// Kernel 1: prep. Blocks 0..63: partial top-k rank counts (16 d-blocks x
// 4 e-ranges, no atomics). Block 64: dtype detection.
// ---------------------------------------------------------------------------
__global__ void prep_kernel(const float* __restrict__ x,
                            const void* __restrict__ perm,
                            const void* __restrict__ masks) {
    int tid = threadIdx.x;

    if (blockIdx.x < 64) {
        __shared__ float a[1024];
        const int dblk = blockIdx.x & 15;        // d-range selector
        const int eh = blockIdx.x >> 4;          // e-range selector 0..3
        const int ebase = eh * 1024;
        const float* f0 = x + (size_t)PBOUND * DDIM;

        for (int i = tid; i < 1024; i += blockDim.x) a[i] = fabsf(f0[ebase + i]);
        __syncthreads();

        int d = dblk * 256 + tid;
        float ad = fabsf(f0[d]);
        int cnt = 0;
#pragma unroll 8
        for (int el = 0; el < 1024; el++) {
            float ae = a[el];
            int e = ebase + el;
            cnt += (int)((ae > ad) || (ae == ad && e < d));
        }
        g_pcnt[eh * DDIM + d] = cnt;
    } else {
        // dtype detection (256 threads)
        __shared__ int s_zero[8], s_f32[8];
        __shared__ unsigned int s_max[8];
        int wid = tid >> 5, lane = tid & 31;

        const int* p32 = (const int*)perm;
        int zeros = 0;
        for (int i = 1 + 2 * tid; i < 4096; i += 512) zeros += (p32[i] == 0);

        const unsigned int* m32 = (const unsigned int*)masks;
        int has_f32 = 0;
        unsigned int maxv = 0;
        for (int i = tid; i < 1024; i += 256) {
            unsigned int v = m32[i];
            if (v == 0x3F800000u) has_f32 = 1;
            if (v > maxv) maxv = v;
        }
#pragma unroll
        for (int off = 16; off > 0; off >>= 1) {
            zeros   += __shfl_down_sync(0xffffffffu, zeros, off);
            has_f32 |= __shfl_down_sync(0xffffffffu, has_f32, off);
            unsigned int o = __shfl_down_sync(0xffffffffu, maxv, off);
            if (o > maxv) maxv = o;
        }
        if (lane == 0) { s_zero[wid] = zeros; s_f32[wid] = has_f32; s_max[wid] = maxv; }
        __syncthreads();
        if (tid == 0) {
            int z = 0, f = 0;
            unsigned int mx = 0;
            for (int i = 0; i < 8; i++) {
                z += s_zero[i];
                f |= s_f32[i];
                if (s_max[i] > mx) mx = s_max[i];
            }
            g_perm_mode = (z >= 1000) ? 8 : 4;
            g_mask_mode = f ? 5 : (mx <= 1u ? 4 : 1);
        }
    }
}

// ---------------------------------------------------------------------------
// Kernel 2: select. Active bitmap + ballot/popc mask counting (coalesced),
// argmax + gate, K compaction (kidx, kcnt, kpad). 1 block, 1024 threads.
// ---------------------------------------------------------------------------
__global__ void select_kernel(const void* __restrict__ masks,
                              const void* __restrict__ perm) {
    __shared__ int counts[NMASK];
    __shared__ unsigned int abm[128];        // 4096-bit active bitmap
    __shared__ int sbest, sflag;
    __shared__ int scan[1024];
    __shared__ int s_inactive;

    const int pmode = g_perm_mode, mmode = g_mask_mode;
    const int tid = threadIdx.x, wid = tid >> 5, lane = tid & 31;

    if (tid < 128) abm[tid] = 0u;
    if (tid == 0) s_inactive = 0x7FFFFFFF;
    __syncthreads();

    // topk flags (sum of 4 partial counts) -> permuted active bitmap
    const int d0 = tid * 4;
#pragma unroll
    for (int q = 0; q < 4; q++) {
        int d = d0 + q;
        int cnt = g_pcnt[d] + g_pcnt[DDIM + d] + g_pcnt[2 * DDIM + d] +
                  g_pcnt[3 * DDIM + d];
        if (cnt < TOPK) {
            int p = (pmode == 8) ? (int)((const long long*)perm)[d]
                                 : ((const int*)perm)[d];
            atomicOr(&abm[p >> 5], 1u << (p & 31));
        }
    }
    __syncthreads();

    // counts[j] = popcount(mask_j AND active); warp w handles rows 2w, 2w+1.
    // Mask reads are coalesced (consecutive p per warp).
#pragma unroll
    for (int r = 0; r < 2; r++) {
        const int j = wid * 2 + r;
        int tot = 0;
        for (int it = 0; it < 128; it++) {
            int p = it * 32 + lane;
            int bit = mask_at(masks, mmode, (size_t)j * DDIM + p);
            unsigned int word = __ballot_sync(0xffffffffu, bit);
            tot += __popc(word & abm[it]);
        }
        if (lane == 0) counts[j] = tot;
    }
    __syncthreads();

    if (tid == 0) {
        int best = 0, bc = counts[0];
        for (int jj = 1; jj < NMASK; jj++)
            if (counts[jj] > bc) { bc = counts[jj]; best = jj; }
        sbest = best;
        sflag = ((float)bc / (float)TOPK >= 0.3f) ? 1 : 0;
    }
    __syncthreads();

    const int best = sbest, flag = sflag;

    // per-thread 4 consecutive columns of the chosen mask
    int act[4], s = 0;
#pragma unroll
    for (int q = 0; q < 4; q++) {
        int a = flag && mask_at(masks, mmode, (size_t)best * DDIM + d0 + q);
        act[q] = a;
        s += a;
    }
#pragma unroll
    for (int q = 0; q < 4; q++)
        if (!act[q]) { atomicMin(&s_inactive, d0 + q); break; }

    scan[tid] = s;
    __syncthreads();
#pragma unroll
    for (int off = 1; off < 1024; off <<= 1) {
        int v = (tid >= off) ? scan[tid - off] : 0;
        __syncthreads();
        scan[tid] += v;
        __syncthreads();
    }
    int pos = scan[tid] - s;
#pragma unroll
    for (int q = 0; q < 4; q++)
        if (act[q]) g_kidx[pos++] = d0 + q;
    __syncthreads();

    if (tid == 0) {
        int cnt = scan[1023];
        int kpad = (cnt + BK - 1) / BK * BK;
        int dummy = (s_inactive == 0x7FFFFFFF) ? 0 : s_inactive;  // inactive col
        for (int q = cnt; q < kpad; q++) g_kidx[q] = dummy;
        g_kpad = kpad;
        g_kcnt = cnt;
    }
}

// ---------------------------------------------------------------------------
// Kernel 3: gathered f32 -> fp16 conversion for BOTH X and W (compacted K).
// Active entries need no mask multiply (fmask==1 by construction); padding
// entries (jc >= kcnt) are zeroed in A, making W padding values irrelevant.
// ---------------------------------------------------------------------------
__device__ __forceinline__ uint32_t pack_half2(float a, float b) {
    __half2 h = __floats2half2_rn(a, b);
    uint32_t u; memcpy(&u, &h, 4); return u;
}

__global__ void convert_kernel(const float* __restrict__ x,
                               const float* __restrict__ w) {
    const int kpad = g_kpad, kcnt = g_kcnt;
    size_t i = (size_t)blockIdx.x * blockDim.x + threadIdx.x;
    int row_id = (int)(i >> 10);        // 0..(MDIM+NDIM-1)
    int jc = ((int)i & 1023) * 4;
    if (jc >= kpad) return;
    int4 kk = ((const int4*)g_kidx)[jc >> 2];

    uint2 v;
    if (row_id < MDIM) {
        const float* row = x + (size_t)row_id * DDIM;
        float v0 = (jc + 0 < kcnt) ? row[kk.x] : 0.0f;
        float v1 = (jc + 1 < kcnt) ? row[kk.y] : 0.0f;
        float v2 = (jc + 2 < kcnt) ? row[kk.z] : 0.0f;
        float v3 = (jc + 3 < kcnt) ? row[kk.w] : 0.0f;
        v.x = pack_half2(v0, v1);
        v.y = pack_half2(v2, v3);
        *(uint2*)(g_Af + (size_t)row_id * DDIM + jc) = v;
    } else {
        const float* row = w + (size_t)(row_id - MDIM) * DDIM;
        v.x = pack_half2(row[kk.x], row[kk.y]);
        v.y = pack_half2(row[kk.z], row[kk.w]);
        *(uint2*)(g_Wf + (size_t)(row_id - MDIM) * DDIM + jc) = v;
    }
}

// ---------------------------------------------------------------------------
// Kernel 4: warp-MMA fp16 single-term GEMM over compacted K.
// 128x128x32 CTA tile, 8 warps (2x4), warp tile 64x32, 4-stage cp.async,
// 2 CTAs/SM. B frags hoisted per tile; A frags software-pipelined in pairs.
// ---------------------------------------------------------------------------
__global__ void __launch_bounds__(256, 2)
gemm_mma_kernel(float* __restrict__ C) {
    extern __shared__ char smem[];
    const uint32_t sb = smem_u32(smem);
    const int tid = threadIdx.x;
    const int wid = tid >> 5;
    const int lane = tid & 31;
    const int warp_m = wid & 1;
    const int warp_n = wid >> 1;

    const int m0 = blockIdx.y * BM;
    const int n0 = blockIdx.x * BN;
    const int NT = g_kpad / BK;          // dynamic k-tile count

    const int lr = tid >> 2;             // 0..63
    const int lch = tid & 3;             // 16B chunk
    const int lc = lch * 8;

    const __half* A = g_Af + (size_t)m0 * DDIM;
    const __half* W = g_Wf + (size_t)n0 * DDIM;

#define LOAD_STAGE(base, kb)                                                   \
    do {                                                                       \
        const __half* sa = A + (size_t)lr * DDIM + (kb) + lc;                  \
        const __half* sw = W + (size_t)lr * DDIM + (kb) + lc;                  \
        cp16((base) + tile_off(lr, lch), sa);                                  \
        cp16((base) + tile_off(lr + 64, lch), sa + (size_t)64 * DDIM);         \
        cp16((base) + TILE_B + tile_off(lr, lch), sw);                         \
        cp16((base) + TILE_B + tile_off(lr + 64, lch), sw + (size_t)64 * DDIM);\
    } while (0)

    // prologue: stages 0..STAGES-2 (guarded for short K)
#pragma unroll
    for (int it = 0; it < STAGES - 1; ++it) {
        if (it < NT) LOAD_STAGE(sb + it * STAGE_B, it * BK);
        cp_commit();
    }

    float acc[4][4][4];
#pragma unroll
    for (int mi = 0; mi < 4; mi++)
#pragma unroll
        for (int nj = 0; nj < 4; nj++)
#pragma unroll
            for (int q = 0; q < 4; q++) acc[mi][nj][q] = 0.0f;

    const int ar = warp_m * 64 + (lane & 15);
    const int br = warp_n * 32 + (lane & 15);
    const int kgrp = lane >> 4;

#pragma unroll 1
    for (int it = 0; it < NT; ++it) {
        cp_wait<STAGES - 2>();
        __syncthreads();   // stage(it) ready; all warps done with old buffer

        if (it + STAGES - 1 < NT)
            LOAD_STAGE(sb + ((it + STAGES - 1) & (STAGES - 1)) * STAGE_B,
                       (it + STAGES - 1) * BK);
        cp_commit();

        const uint32_t stg = sb + (it & (STAGES - 1)) * STAGE_B;

        // hoist ALL B fragments for this 32-K tile (4 x ldsm4 = 16 regs)
        uint32_t bfr[4][4];
#pragma unroll
        for (int g = 0; g < 2; g++)
#pragma unroll
            for (int ni = 0; ni < 2; ni++)
                ldsm4(bfr[g * 2 + ni],
                      stg + TILE_B + tile_off(br + ni * 16, g * 2 + kgrp));

        // A fragments: 4 pipeline steps of (g, mi-pair), double-buffered
        // step s: g = s>>1, mp = s&1
        uint32_t af[2][2][4];
#pragma unroll
        for (int q = 0; q < 2; q++)
            ldsm4(af[0][q], stg + tile_off(ar + q * 16, kgrp));   // (g=0,mp=0)

#pragma unroll
        for (int s = 0; s < 4; s++) {
            const int g = s >> 1, mp = s & 1, buf = s & 1;
            if (s < 3) {
                const int ng = (s + 1) >> 1, nmp = (s + 1) & 1;
#pragma unroll
                for (int q = 0; q < 2; q++)
                    ldsm4(af[buf ^ 1][q],
                          stg + tile_off(ar + (nmp * 2 + q) * 16, ng * 2 + kgrp));
            }
#pragma unroll
            for (int q = 0; q < 2; q++) {
                const int mi = mp * 2 + q;
#pragma unroll
                for (int nj = 0; nj < 4; nj++) {
                    const int ni = nj >> 1, sub = nj & 1;
                    mma_f16(acc[mi][nj], af[buf][q],
                            bfr[g * 2 + ni][sub], bfr[g * 2 + ni][sub + 2]);
                }
            }
        }
    }

    // epilogue: always write (zeros when gate is off / NT==0)
    const int crow = m0 + warp_m * 64 + (lane >> 2);
    const int ccol = n0 + warp_n * 32 + (lane & 3) * 2;
#pragma unroll
    for (int mi = 0; mi < 4; mi++) {
#pragma unroll
        for (int nj = 0; nj < 4; nj++) {
            float* p0 = C + (size_t)(crow + mi * 16) * NDIM + ccol + nj * 8;
            float* p1 = p0 + (size_t)8 * NDIM;
            *(float2*)p0 = make_float2(acc[mi][nj][0], acc[mi][nj][1]);
            *(float2*)p1 = make_float2(acc[mi][nj][2], acc[mi][nj][3]);
        }
    }
#undef LOAD_STAGE
}

// ---------------------------------------------------------------------------
// Launch
// ---------------------------------------------------------------------------
extern "C" void kernel_launch(void* const* d_in, const int* in_sizes, int n_in,
                              void* d_out, int out_size) {
    const float* x     = (const float*)d_in[0];
    const float* w     = (const float*)d_in[1];
    const void*  masks = d_in[2];
    const void*  perm  = d_in[3];
    float*       out   = (float*)d_out;

    cudaFuncSetAttribute(gemm_mma_kernel,
                         cudaFuncAttributeMaxDynamicSharedMemorySize, SMEM_TOTAL);

    prep_kernel<<<65, 256>>>(x, perm, masks);   // topk partials (0-63) + detect (64)
    select_kernel<<<1, 1024>>>(masks, perm);
    convert_kernel<<<((MDIM + NDIM) * 1024) / 256, 256>>>(x, w);

    dim3 grid(NDIM / BN, MDIM / BM);   // (32, 32)
    gemm_mma_kernel<<<grid, 256, SMEM_TOTAL>>>(out);
}